// round 13
// baseline (speedup 1.0000x reference)
#include <cuda_runtime.h>
#include <cuda_bf16.h>
#include <math.h>

#define BATCH 2048
#define LQ 32
#define LD 256
#define EMBD 50
#define KN 21
#define L2E 1.4426950408889634f
#define TSTR 36        // u32 words per tile row (64 bf16 cols = 32 words + 4 pad)
#define XPS 17         // u64 stride per thread in xp overlay (conflict-free)

typedef unsigned long long u64;
typedef unsigned int u32;

__device__ float g_feat[2 * BATCH * KN];

__device__ __forceinline__ float ex2(float a) {
    float r; asm("ex2.approx.ftz.f32 %0, %1;" : "=f"(r) : "f"(a)); return r;
}
__device__ __forceinline__ u64 fma2(u64 a, u64 b, u64 c) {
    u64 r; asm("fma.rn.f32x2 %0, %1, %2, %3;" : "=l"(r) : "l"(a), "l"(b), "l"(c)); return r;
}
__device__ __forceinline__ u64 mul2(u64 a, u64 b) {
    u64 r; asm("mul.rn.f32x2 %0, %1, %2;" : "=l"(r) : "l"(a), "l"(b)); return r;
}
__device__ __forceinline__ u64 pack2(float lo, float hi) {
    u64 r; asm("mov.b64 %0, {%1, %2};" : "=l"(r) : "f"(lo), "f"(hi)); return r;
}
__device__ __forceinline__ void unpack2(u64 v, float& lo, float& hi) {
    asm("mov.b64 {%0, %1}, %2;" : "=f"(lo), "=f"(hi) : "l"(v));
}
__device__ __forceinline__ u64 bcast2(float c) { return pack2(c, c); }
__device__ __forceinline__ u64 ex2p(u64 m) {
    float a, b; unpack2(m, a, b);
    return pack2(ex2(a), ex2(b));
}

__device__ __forceinline__ float CKf(int k) {
    switch (k) {
        case 0: return 2.5261638e-20f;
        case 1: return 2.0469717e-16f;
        case 2: return 6.1019367e-13f;
        case 3: return 6.6915860e-10f;
        case 4: return 2.6995785e-07f;
        case 5: return 4.0065297e-05f;
        case 6: return 2.1874905e-03f;
        case 7: return 4.3936934e-02f;
        case 8: return 3.2465247e-01f;
        default: return 8.8249690e-01f;
    }
}

__device__ __forceinline__ void mma_bf16(float& c0, float& c1, float& c2, float& c3,
                                         u32 a0, u32 a1, u32 a2, u32 a3,
                                         u32 b0, u32 b1)
{
    asm("mma.sync.aligned.m16n8k16.row.col.f32.bf16.bf16.f32 "
        "{%0,%1,%2,%3},{%4,%5,%6,%7},{%8,%9},{%0,%1,%2,%3};"
        : "+f"(c0), "+f"(c1), "+f"(c2), "+f"(c3)
        : "r"(a0), "r"(a1), "r"(a2), "r"(a3), "r"(b0), "r"(b1));
}

__device__ __forceinline__ void ldsm4(u32& r0, u32& r1, u32& r2, u32& r3, u32 saddr)
{
    asm volatile("ldmatrix.sync.aligned.m8n8.x4.shared.b16 {%0,%1,%2,%3}, [%4];"
                 : "=r"(r0), "=r"(r1), "=r"(r2), "=r"(r3) : "r"(saddr));
}

extern "C" __global__ void __launch_bounds__(256, 2)
knrm_main(const float* __restrict__ emb,
          const int* __restrict__ query1, const int* __restrict__ doc1,
          const int* __restrict__ query2, const int* __restrict__ doc2,
          int boff)
{
    extern __shared__ u32 smw[];
    u32* dh = smw;                       // [256][36] bf16x2 hi  (xp overlay later)
    u32* dl = dh + LD * TSTR;            // [256][36] bf16x2 lo  (ssum/pfeat overlay later)
    u32* qh = dl + LD * TSTR;            // [32][36]
    u32* ql = qh + LQ * TSTR;            // [32][36]
    u64*  xps    = (u64*)smw;                  // overlay over dh after MMA
    float* ssum  = (float*)dl;                 // overlay over dl after MMA: [4][32][21]
    float* pfeat = ssum + 4 * LQ * KN;         // [672]

    const int b    = blockIdx.x + boff;
    const int pair = blockIdx.y;
    const int* qidx = pair ? query2 : query1;
    const int* didx = pair ? doc2   : doc1;
    const int tid  = threadIdx.x;
    const int w    = tid >> 5;
    const int lane = tid & 31;

    // ---- coalesced warp-cooperative gather + normalize + bf16 hi/lo split ----
    // warp w owns rows [36w, 36w+36): rows 0..255 = doc, 256..287 = query.
    {
        // prefetch tokens: lane l -> row 36w+l ; lanes 0..3 -> rows 36w+32+l
        int r0 = 36 * w + lane;
        int tok0 = (r0 < LD) ? didx[b * LD + r0] : qidx[b * LQ + (r0 - LD)];
        int r1 = 36 * w + 32 + lane;
        int tok1 = 0;
        if (lane < 4)
            tok1 = (r1 < LD) ? didx[b * LD + r1] : qidx[b * LQ + (r1 - LD)];

        #pragma unroll
        for (int j = 0; j < 36; j++) {
            int tok = (j < 32) ? __shfl_sync(0xffffffffu, tok0, j)
                               : __shfl_sync(0xffffffffu, tok1, j - 32);
            int row = 36 * w + j;
            // lanes 0..24 load one float2 each (coalesced 200B = 2 lines)
            float2 e = make_float2(0.0f, 0.0f);
            if (lane < 25)
                e = ((const float2*)(emb + (size_t)tok * EMBD))[lane];
            float ss = fmaf(e.x, e.x, e.y * e.y);
            #pragma unroll
            for (int off = 16; off > 0; off >>= 1)
                ss += __shfl_xor_sync(0xffffffffu, ss, off);
            float scale = 1.0f / (sqrtf(ss) + 1e-13f);

            u32* ht; u32* lt; int trow;
            if (row < LD) { ht = dh; lt = dl; trow = row; }
            else          { ht = qh; lt = ql; trow = row - LD; }

            if (lane < 25) {
                float x0 = e.x * scale, x1 = e.y * scale;
                __nv_bfloat16 h0 = __float2bfloat16_rn(x0);
                __nv_bfloat16 h1 = __float2bfloat16_rn(x1);
                float rr0 = x0 - __bfloat162float(h0);
                float rr1 = x1 - __bfloat162float(h1);
                __nv_bfloat16 l0 = __float2bfloat16_rn(rr0);
                __nv_bfloat16 l1 = __float2bfloat16_rn(rr1);
                u32 hp = (u32)*(unsigned short*)&h0 | ((u32)*(unsigned short*)&h1 << 16);
                u32 lp = (u32)*(unsigned short*)&l0 | ((u32)*(unsigned short*)&l1 << 16);
                ht[trow * TSTR + lane] = hp;
                lt[trow * TSTR + lane] = lp;
            } else {   // zero K-pad words 25..31 (ldmatrix reads words 0..31)
                ht[trow * TSTR + lane] = 0u;
                lt[trow * TSTR + lane] = 0u;
            }
        }
    }
    __syncthreads();

    // ==== tensor-core matmul: warp w -> q-tile m16 at qm, d-tile n64 at dt*64 ====
    const int qm = (w & 1) * 16;
    const int dt = w >> 1;                  // 0..3
    const int g  = lane >> 2;               // 0..7
    const int t  = lane & 3;                // 0..3

    float C[8][4];
    #pragma unroll
    for (int nt = 0; nt < 8; nt++)
        #pragma unroll
        for (int i = 0; i < 4; i++) C[nt][i] = 0.0f;

    // ldmatrix lane addresses (byte offsets in shared space)
    const u32 qh_s = (u32)__cvta_generic_to_shared(qh);
    const u32 ql_s = (u32)__cvta_generic_to_shared(ql);
    const u32 dh_s = (u32)__cvta_generic_to_shared(dh);
    const u32 dl_s = (u32)__cvta_generic_to_shared(dl);

    const int arow  = qm + (lane & 15);
    const int acolw = (lane & 16) >> 2;                        // 0 or 4 words
    const u32 a_ofs = (u32)((arow * TSTR + acolw) * 4);

    const int brow  = dt * 64 + (lane & 7) + ((lane & 16) >> 1);  // +8 for lanes>=16
    const int bcolw = (lane & 8) >> 1;                            // 0 or 4 words
    const u32 b_ofs = (u32)((brow * TSTR + bcolw) * 4);

    #pragma unroll
    for (int ks = 0; ks < 4; ks++) {
        const u32 kb = (u32)(ks * 8 * 4);          // k16 step, bytes
        u32 ah0, ah1, ah2, ah3, al0, al1, al2, al3;
        ldsm4(ah0, ah1, ah2, ah3, qh_s + a_ofs + kb);
        ldsm4(al0, al1, al2, al3, ql_s + a_ofs + kb);
        #pragma unroll
        for (int np = 0; np < 4; np++) {           // 2 n8-tiles per ldmatrix.x4
            const u32 nb = b_ofs + kb + (u32)(np * 16 * TSTR * 4);
            u32 bh0, bh1, bh2, bh3, bl0, bl1, bl2, bl3;
            ldsm4(bh0, bh1, bh2, bh3, dh_s + nb);
            ldsm4(bl0, bl1, bl2, bl3, dl_s + nb);
            mma_bf16(C[2*np][0], C[2*np][1], C[2*np][2], C[2*np][3],
                     ah0, ah1, ah2, ah3, bh0, bh1);
            mma_bf16(C[2*np][0], C[2*np][1], C[2*np][2], C[2*np][3],
                     ah0, ah1, ah2, ah3, bl0, bl1);
            mma_bf16(C[2*np][0], C[2*np][1], C[2*np][2], C[2*np][3],
                     al0, al1, al2, al3, bh0, bh1);
            mma_bf16(C[2*np+1][0], C[2*np+1][1], C[2*np+1][2], C[2*np+1][3],
                     ah0, ah1, ah2, ah3, bh2, bh3);
            mma_bf16(C[2*np+1][0], C[2*np+1][1], C[2*np+1][2], C[2*np+1][3],
                     ah0, ah1, ah2, ah3, bl2, bl3);
            mma_bf16(C[2*np+1][0], C[2*np+1][1], C[2*np+1][2], C[2*np+1][3],
                     al0, al1, al2, al3, bh2, bh3);
        }
    }
    __syncthreads();   // all warps done reading dh/dl -> overlays safe

    // ---- park x pairs in smem (frees regs for eval constants) ----
    // pair m: (q-row qm+g [lo], q-row qm+g+8 [hi]), d = dt*64 + (m/2)*8 + 2*t + (m&1)
    {
        u64* xbase = xps + tid * XPS;
        #pragma unroll
        for (int nt = 0; nt < 8; nt++) {
            xbase[2 * nt]     = pack2(C[nt][0], C[nt][2]);
            xbase[2 * nt + 1] = pack2(C[nt][1], C[nt][3]);
        }
    }

    // ---- eval: 20 Gaussian kernels via 2 packed chains + exact-match count ----
    const u64 cZ  = bcast2(-50.0f * L2E);
    const u64 c10 = bcast2(10.0f * L2E);
    const u64 cA  = bcast2(-95.0f * L2E);   // chain A seed mu = -0.95
    const u64 cB  = bcast2(5.0f * L2E);     // chain B seed mu =  0.05
    const int IB09 = 0x3F666666;            // __float_as_int(0.9f)

    u64 Kc[10];
    #pragma unroll
    for (int j = 0; j < 10; j++) Kc[j] = bcast2(CKf(j));

    u64 ks2[20];
    #pragma unroll
    for (int k = 0; k < 20; k++) ks2[k] = 0ull;
    int icl = 0, ich = 0;

    const u64* xbase = xps + tid * XPS;
    #pragma unroll
    for (int m = 0; m < 16; m++) {
        u64 x2 = xbase[m];
        {
            int ilo = (int)(unsigned)(x2 & 0xffffffffu);
            int ihi = (int)(unsigned)(x2 >> 32);
            icl += (ilo > IB09);
            ich += (ihi > IB09);
        }
        u64 y2 = mul2(x2, x2);
        u64 z2 = mul2(y2, cZ);
        u64 r2 = ex2p(mul2(x2, c10));
        u64 tA = ex2p(fma2(x2, cA, z2));
        u64 tB = ex2p(fma2(x2, cB, z2));

        // chain A uses CK(j) = Kc[j]; chain B uses CK(10+j) = CK(9-j) = Kc[9-j]
        #pragma unroll
        for (int j = 0; j < 10; j++) {
            ks2[j]      = fma2(tA, Kc[j],     ks2[j]);
            ks2[10 + j] = fma2(tB, Kc[9 - j], ks2[10 + j]);
            if (j < 9) { tA = mul2(tA, r2); tB = mul2(tB, r2); }
        }
    }

    // ---- reduce over the 4 lanes (t = 0..3) sharing each g ----
    float sl[KN], sh[KN];
    #pragma unroll
    for (int k = 0; k < 20; k++) unpack2(ks2[k], sl[k], sh[k]);
    sl[20] = (float)icl; sh[20] = (float)ich;
    #pragma unroll
    for (int k = 0; k < KN; k++) {
        float a = sl[k], c = sh[k];
        a += __shfl_xor_sync(0xffffffffu, a, 1);
        a += __shfl_xor_sync(0xffffffffu, a, 2);
        c += __shfl_xor_sync(0xffffffffu, c, 1);
        c += __shfl_xor_sync(0xffffffffu, c, 2);
        sl[k] = a; sh[k] = c;
    }
    {
        float* d0 = ssum + (dt * LQ + qm + g) * KN;
        float* d1 = ssum + (dt * LQ + qm + g + 8) * KN;
        #pragma unroll
        for (int k = 0; k < KN; k++)
            if ((k & 3) == t) { d0[k] = sl[k]; d1[k] = sh[k]; }
    }
    __syncthreads();

    // ---- sum d-tiles, log1p per (q,k) ----
    for (int idx = tid; idx < LQ * KN; idx += 256) {
        float v = ssum[idx] + ssum[LQ * KN + idx]
                + ssum[2 * LQ * KN + idx] + ssum[3 * LQ * KN + idx];
        pfeat[idx] = log1pf(v);
    }
    __syncthreads();
    if (tid < KN) {
        float f = 0.0f;
        #pragma unroll
        for (int q = 0; q < LQ; q++)
            f += pfeat[q * KN + tid];
        g_feat[(pair * BATCH + b) * KN + tid] = f;
    }
}

extern "C" __global__ void knrm_mlp(const float* __restrict__ w0, const float* __restrict__ b0,
                                    const float* __restrict__ w1, const float* __restrict__ b1,
                                    const float* __restrict__ w2, const float* __restrict__ b2,
                                    float* __restrict__ out)
{
    int b = blockIdx.x * blockDim.x + threadIdx.x;
    if (b >= BATCH) return;

    float logit[2];
    #pragma unroll
    for (int p = 0; p < 2; p++) {
        const float* f = g_feat + (p * BATCH + b) * KN;
        float h0[10];
        #pragma unroll
        for (int j = 0; j < 10; j++) {
            float s = b0[j];
            #pragma unroll
            for (int k = 0; k < KN; k++) s = fmaf(w0[j * KN + k], f[k], s);
            h0[j] = fmaxf(s, 0.0f);
        }
        float h1[5];
        #pragma unroll
        for (int j = 0; j < 5; j++) {
            float s = b1[j];
            #pragma unroll
            for (int k = 0; k < 10; k++) s = fmaf(w1[j * 10 + k], h0[k], s);
            h1[j] = fmaxf(s, 0.0f);
        }
        float s = b2[0];
        #pragma unroll
        for (int k = 0; k < 5; k++) s = fmaf(w2[k], h1[k], s);
        logit[p] = s;
    }
    float z = logit[0] - logit[1];
    out[b] = 1.0f / (1.0f + expf(-z));
}

extern "C" void kernel_launch(void* const* d_in, const int* in_sizes, int n_in,
                              void* d_out, int out_size)
{
    const float* emb = (const float*)d_in[0];
    const float* w0  = (const float*)d_in[1];
    const float* b0  = (const float*)d_in[2];
    const float* w1  = (const float*)d_in[3];
    const float* b1  = (const float*)d_in[4];
    const float* w2  = (const float*)d_in[5];
    const float* b2  = (const float*)d_in[6];
    const int* query1 = (const int*)d_in[7];
    const int* doc1   = (const int*)d_in[8];
    const int* query2 = (const int*)d_in[9];
    const int* doc2   = (const int*)d_in[10];
    float* out = (float*)d_out;

    // smem: tiles only (ssum/pfeat/xps overlay the dead tile regions)
    const int smem_bytes = (LD + LQ) * TSTR * 2 * 4;
    cudaFuncSetAttribute(knrm_main, cudaFuncAttributeMaxDynamicSharedMemorySize, smem_bytes);

    knrm_main<<<dim3(BATCH / 2, 2), 256, smem_bytes>>>(emb, query1, doc1, query2, doc2, 0);
    knrm_main<<<dim3(BATCH / 2, 2), 256, smem_bytes>>>(emb, query1, doc1, query2, doc2, BATCH / 2);
    knrm_mlp<<<16, 128>>>(w0, b0, w1, b1, w2, b2, out);
}

// round 14
// speedup vs baseline: 1.7962x; 1.7962x over previous
#include <cuda_runtime.h>
#include <cuda_bf16.h>
#include <math.h>

#define BATCH 2048
#define LQ 32
#define LD 256
#define EMBD 50
#define KN 21
#define L2E 1.4426950408889634f
#define TSTR 36        // u32 words per tile row (64 bf16 cols = 32 words + 4 pad)
#define XPS 17         // u64 stride per thread in xp overlay (conflict-free)

typedef unsigned long long u64;
typedef unsigned int u32;

__device__ float g_feat[2 * BATCH * KN];

__device__ __forceinline__ float ex2(float a) {
    float r; asm("ex2.approx.ftz.f32 %0, %1;" : "=f"(r) : "f"(a)); return r;
}
__device__ __forceinline__ u64 fma2(u64 a, u64 b, u64 c) {
    u64 r; asm("fma.rn.f32x2 %0, %1, %2, %3;" : "=l"(r) : "l"(a), "l"(b), "l"(c)); return r;
}
__device__ __forceinline__ u64 mul2(u64 a, u64 b) {
    u64 r; asm("mul.rn.f32x2 %0, %1, %2;" : "=l"(r) : "l"(a), "l"(b)); return r;
}
__device__ __forceinline__ u64 pack2(float lo, float hi) {
    u64 r; asm("mov.b64 %0, {%1, %2};" : "=l"(r) : "f"(lo), "f"(hi)); return r;
}
__device__ __forceinline__ void unpack2(u64 v, float& lo, float& hi) {
    asm("mov.b64 {%0, %1}, %2;" : "=f"(lo), "=f"(hi) : "l"(v));
}
__device__ __forceinline__ u64 bcast2(float c) { return pack2(c, c); }
__device__ __forceinline__ u64 ex2p(u64 m) {
    float a, b; unpack2(m, a, b);
    return pack2(ex2(a), ex2(b));
}

__device__ __forceinline__ float CKf(int k) {
    switch (k) {
        case 0: return 2.5261638e-20f;
        case 1: return 2.0469717e-16f;
        case 2: return 6.1019367e-13f;
        case 3: return 6.6915860e-10f;
        case 4: return 2.6995785e-07f;
        case 5: return 4.0065297e-05f;
        case 6: return 2.1874905e-03f;
        case 7: return 4.3936934e-02f;
        case 8: return 3.2465247e-01f;
        default: return 8.8249690e-01f;
    }
}

__device__ __forceinline__ void mma_bf16(float& c0, float& c1, float& c2, float& c3,
                                         u32 a0, u32 a1, u32 a2, u32 a3,
                                         u32 b0, u32 b1)
{
    asm("mma.sync.aligned.m16n8k16.row.col.f32.bf16.bf16.f32 "
        "{%0,%1,%2,%3},{%4,%5,%6,%7},{%8,%9},{%0,%1,%2,%3};"
        : "+f"(c0), "+f"(c1), "+f"(c2), "+f"(c3)
        : "r"(a0), "r"(a1), "r"(a2), "r"(a3), "r"(b0), "r"(b1));
}

__device__ __forceinline__ void ldsm4(u32& r0, u32& r1, u32& r2, u32& r3, u32 saddr)
{
    asm volatile("ldmatrix.sync.aligned.m8n8.x4.shared.b16 {%0,%1,%2,%3}, [%4];"
                 : "=r"(r0), "=r"(r1), "=r"(r2), "=r"(r3) : "r"(saddr));
}

extern "C" __global__ void __launch_bounds__(256, 2)
knrm_main(const float* __restrict__ emb,
          const int* __restrict__ query1, const int* __restrict__ doc1,
          const int* __restrict__ query2, const int* __restrict__ doc2,
          int boff)
{
    extern __shared__ u32 smw[];
    u32* dh = smw;                       // [256][36] bf16x2 hi  (xp overlay later)
    u32* dl = dh + LD * TSTR;            // [256][36] bf16x2 lo  (ssum/pfeat overlay later)
    u32* qh = dl + LD * TSTR;            // [32][36]
    u32* ql = qh + LQ * TSTR;            // [32][36]
    u64*  xps    = (u64*)smw;                  // overlay over dh after MMA
    float* ssum  = (float*)dl;                 // overlay over dl after MMA: [4][32][21]
    float* pfeat = ssum + 4 * LQ * KN;         // [672]

    const int b    = blockIdx.x + boff;
    const int pair = blockIdx.y;
    const int* qidx = pair ? query2 : query1;
    const int* didx = pair ? doc2   : doc1;
    const int tid  = threadIdx.x;
    const int w    = tid >> 5;
    const int lane = tid & 31;

    // ---- gather: warp w owns rows [36w, 36w+36); 8 lanes per row, 4 rows/group ----
    {
        // token prefetch: lane l -> row 36w+l ; lanes 0..3 -> rows 36w+32+l
        int r0 = 36 * w + lane;
        int tok0 = (r0 < LD) ? didx[b * LD + r0] : qidx[b * LQ + (r0 - LD)];
        int tok1 = 0;
        if (lane < 4) {
            int r1 = 36 * w + 32 + lane;
            tok1 = (r1 < LD) ? didx[b * LD + r1] : qidx[b * LQ + (r1 - LD)];
        }

        const int rr  = lane >> 3;      // row within 4-row group (0..3)
        const int sub = lane & 7;       // float2 sub-index within row

        #pragma unroll
        for (int ch = 0; ch < 3; ch++) {          // 3 chunks x 3 groups (MLP=12)
            float2 e[3][4];
            #pragma unroll
            for (int gg = 0; gg < 3; gg++) {
                const int g  = ch * 3 + gg;        // group 0..8
                const int rl = 4 * g + rr;         // local row 0..35
                int tk = (g < 8) ? __shfl_sync(0xffffffffu, tok0, rl)
                                 : __shfl_sync(0xffffffffu, tok1, rr);
                const float2* rp = (const float2*)(emb + (size_t)tk * EMBD);
                #pragma unroll
                for (int k = 0; k < 4; k++) {
                    int c2 = sub + 8 * k;          // float2 col 0..24 valid
                    e[gg][k] = (c2 < 25) ? rp[c2] : make_float2(0.0f, 0.0f);
                }
            }
            #pragma unroll
            for (int gg = 0; gg < 3; gg++) {
                const int g   = ch * 3 + gg;
                const int row = 36 * w + 4 * g + rr;
                float ss = 0.0f;
                #pragma unroll
                for (int k = 0; k < 4; k++)
                    ss += fmaf(e[gg][k].x, e[gg][k].x, e[gg][k].y * e[gg][k].y);
                ss += __shfl_xor_sync(0xffffffffu, ss, 1);
                ss += __shfl_xor_sync(0xffffffffu, ss, 2);
                ss += __shfl_xor_sync(0xffffffffu, ss, 4);
                float scale = 1.0f / (sqrtf(ss) + 1e-13f);

                u32 *ht, *lt; int trow;
                if (row < LD) { ht = dh; lt = dl; trow = row; }
                else          { ht = qh; lt = ql; trow = row - LD; }
                u32* hrow = ht + trow * TSTR;
                u32* lrow = lt + trow * TSTR;

                #pragma unroll
                for (int k = 0; k < 4; k++) {
                    int c2 = sub + 8 * k;
                    if (c2 < 25) {
                        float x0 = e[gg][k].x * scale, x1 = e[gg][k].y * scale;
                        __nv_bfloat16 h0 = __float2bfloat16_rn(x0);
                        __nv_bfloat16 h1 = __float2bfloat16_rn(x1);
                        float q0 = x0 - __bfloat162float(h0);
                        float q1 = x1 - __bfloat162float(h1);
                        __nv_bfloat16 l0 = __float2bfloat16_rn(q0);
                        __nv_bfloat16 l1 = __float2bfloat16_rn(q1);
                        u32 hp = (u32)*(unsigned short*)&h0 | ((u32)*(unsigned short*)&h1 << 16);
                        u32 lp = (u32)*(unsigned short*)&l0 | ((u32)*(unsigned short*)&l1 << 16);
                        hrow[c2] = hp;
                        lrow[c2] = lp;
                    }
                }
                if (sub > 0) {   // zero K-pad words 25..31
                    hrow[24 + sub] = 0u;
                    lrow[24 + sub] = 0u;
                }
            }
        }
    }
    __syncthreads();

    // ==== tensor-core matmul: warp w -> q-tile m16 at qm, d-tile n64 at dt*64 ====
    const int qm = (w & 1) * 16;
    const int dt = w >> 1;                  // 0..3
    const int g  = lane >> 2;               // 0..7
    const int t  = lane & 3;                // 0..3

    float C[8][4];
    #pragma unroll
    for (int nt = 0; nt < 8; nt++)
        #pragma unroll
        for (int i = 0; i < 4; i++) C[nt][i] = 0.0f;

    const u32 qh_s = (u32)__cvta_generic_to_shared(qh);
    const u32 ql_s = (u32)__cvta_generic_to_shared(ql);
    const u32 dh_s = (u32)__cvta_generic_to_shared(dh);
    const u32 dl_s = (u32)__cvta_generic_to_shared(dl);

    const int arow  = qm + (lane & 15);
    const int acolw = (lane & 16) >> 2;                        // 0 or 4 words
    const u32 a_ofs = (u32)((arow * TSTR + acolw) * 4);

    const int brow  = dt * 64 + (lane & 7) + ((lane & 16) >> 1);  // +8 for lanes>=16
    const int bcolw = (lane & 8) >> 1;                            // 0 or 4 words
    const u32 b_ofs = (u32)((brow * TSTR + bcolw) * 4);

    #pragma unroll
    for (int ks = 0; ks < 4; ks++) {
        const u32 kb = (u32)(ks * 8 * 4);          // k16 step, bytes
        u32 ah0, ah1, ah2, ah3, al0, al1, al2, al3;
        ldsm4(ah0, ah1, ah2, ah3, qh_s + a_ofs + kb);
        ldsm4(al0, al1, al2, al3, ql_s + a_ofs + kb);
        #pragma unroll
        for (int np = 0; np < 4; np++) {           // 2 n8-tiles per ldmatrix.x4
            const u32 nb = b_ofs + kb + (u32)(np * 16 * TSTR * 4);
            u32 bh0, bh1, bh2, bh3, bl0, bl1, bl2, bl3;
            ldsm4(bh0, bh1, bh2, bh3, dh_s + nb);
            ldsm4(bl0, bl1, bl2, bl3, dl_s + nb);
            mma_bf16(C[2*np][0], C[2*np][1], C[2*np][2], C[2*np][3],
                     ah0, ah1, ah2, ah3, bh0, bh1);
            mma_bf16(C[2*np][0], C[2*np][1], C[2*np][2], C[2*np][3],
                     ah0, ah1, ah2, ah3, bl0, bl1);
            mma_bf16(C[2*np][0], C[2*np][1], C[2*np][2], C[2*np][3],
                     al0, al1, al2, al3, bh0, bh1);
            mma_bf16(C[2*np+1][0], C[2*np+1][1], C[2*np+1][2], C[2*np+1][3],
                     ah0, ah1, ah2, ah3, bh2, bh3);
            mma_bf16(C[2*np+1][0], C[2*np+1][1], C[2*np+1][2], C[2*np+1][3],
                     ah0, ah1, ah2, ah3, bl2, bl3);
            mma_bf16(C[2*np+1][0], C[2*np+1][1], C[2*np+1][2], C[2*np+1][3],
                     al0, al1, al2, al3, bh2, bh3);
        }
    }
    __syncthreads();   // all warps done reading dh/dl -> overlays safe

    // ---- park x pairs in smem (frees regs for eval constants) ----
    {
        u64* xbase = xps + tid * XPS;
        #pragma unroll
        for (int nt = 0; nt < 8; nt++) {
            xbase[2 * nt]     = pack2(C[nt][0], C[nt][2]);
            xbase[2 * nt + 1] = pack2(C[nt][1], C[nt][3]);
        }
    }

    // ---- eval: 20 Gaussian kernels via 2 packed chains + exact-match count ----
    const u64 cZ  = bcast2(-50.0f * L2E);
    const u64 c10 = bcast2(10.0f * L2E);
    const u64 cA  = bcast2(-95.0f * L2E);   // chain A seed mu = -0.95
    const u64 cB  = bcast2(5.0f * L2E);     // chain B seed mu =  0.05
    const int IB09 = 0x3F666666;            // __float_as_int(0.9f)

    u64 Kc[10];
    #pragma unroll
    for (int j = 0; j < 10; j++) Kc[j] = bcast2(CKf(j));

    u64 ks2[20];
    #pragma unroll
    for (int k = 0; k < 20; k++) ks2[k] = 0ull;
    int icl = 0, ich = 0;

    const u64* xbase = xps + tid * XPS;
    #pragma unroll
    for (int m = 0; m < 16; m++) {
        u64 x2 = xbase[m];
        {
            int ilo = (int)(unsigned)(x2 & 0xffffffffu);
            int ihi = (int)(unsigned)(x2 >> 32);
            icl += (ilo > IB09);
            ich += (ihi > IB09);
        }
        u64 y2 = mul2(x2, x2);
        u64 z2 = mul2(y2, cZ);
        u64 r2 = ex2p(mul2(x2, c10));
        u64 tA = ex2p(fma2(x2, cA, z2));
        u64 tB = ex2p(fma2(x2, cB, z2));

        // chain A uses CK(j) = Kc[j]; chain B uses CK(10+j) = CK(9-j) = Kc[9-j]
        #pragma unroll
        for (int j = 0; j < 10; j++) {
            ks2[j]      = fma2(tA, Kc[j],     ks2[j]);
            ks2[10 + j] = fma2(tB, Kc[9 - j], ks2[10 + j]);
            if (j < 9) { tA = mul2(tA, r2); tB = mul2(tB, r2); }
        }
    }

    // ---- reduce over the 4 lanes (t = 0..3) sharing each g ----
    float sl[KN], sh[KN];
    #pragma unroll
    for (int k = 0; k < 20; k++) unpack2(ks2[k], sl[k], sh[k]);
    sl[20] = (float)icl; sh[20] = (float)ich;
    #pragma unroll
    for (int k = 0; k < KN; k++) {
        float a = sl[k], c = sh[k];
        a += __shfl_xor_sync(0xffffffffu, a, 1);
        a += __shfl_xor_sync(0xffffffffu, a, 2);
        c += __shfl_xor_sync(0xffffffffu, c, 1);
        c += __shfl_xor_sync(0xffffffffu, c, 2);
        sl[k] = a; sh[k] = c;
    }
    {
        float* d0 = ssum + (dt * LQ + qm + g) * KN;
        float* d1 = ssum + (dt * LQ + qm + g + 8) * KN;
        #pragma unroll
        for (int k = 0; k < KN; k++)
            if ((k & 3) == t) { d0[k] = sl[k]; d1[k] = sh[k]; }
    }
    __syncthreads();

    // ---- sum d-tiles, log1p per (q,k) ----
    for (int idx = tid; idx < LQ * KN; idx += 256) {
        float v = ssum[idx] + ssum[LQ * KN + idx]
                + ssum[2 * LQ * KN + idx] + ssum[3 * LQ * KN + idx];
        pfeat[idx] = log1pf(v);
    }
    __syncthreads();
    if (tid < KN) {
        float f = 0.0f;
        #pragma unroll
        for (int q = 0; q < LQ; q++)
            f += pfeat[q * KN + tid];
        g_feat[(pair * BATCH + b) * KN + tid] = f;
    }
}

extern "C" __global__ void knrm_mlp(const float* __restrict__ w0, const float* __restrict__ b0,
                                    const float* __restrict__ w1, const float* __restrict__ b1,
                                    const float* __restrict__ w2, const float* __restrict__ b2,
                                    float* __restrict__ out)
{
    int b = blockIdx.x * blockDim.x + threadIdx.x;
    if (b >= BATCH) return;

    float logit[2];
    #pragma unroll
    for (int p = 0; p < 2; p++) {
        const float* f = g_feat + (p * BATCH + b) * KN;
        float h0[10];
        #pragma unroll
        for (int j = 0; j < 10; j++) {
            float s = b0[j];
            #pragma unroll
            for (int k = 0; k < KN; k++) s = fmaf(w0[j * KN + k], f[k], s);
            h0[j] = fmaxf(s, 0.0f);
        }
        float h1[5];
        #pragma unroll
        for (int j = 0; j < 5; j++) {
            float s = b1[j];
            #pragma unroll
            for (int k = 0; k < 10; k++) s = fmaf(w1[j * 10 + k], h0[k], s);
            h1[j] = fmaxf(s, 0.0f);
        }
        float s = b2[0];
        #pragma unroll
        for (int k = 0; k < 5; k++) s = fmaf(w2[k], h1[k], s);
        logit[p] = s;
    }
    float z = logit[0] - logit[1];
    out[b] = 1.0f / (1.0f + expf(-z));
}

extern "C" void kernel_launch(void* const* d_in, const int* in_sizes, int n_in,
                              void* d_out, int out_size)
{
    const float* emb = (const float*)d_in[0];
    const float* w0  = (const float*)d_in[1];
    const float* b0  = (const float*)d_in[2];
    const float* w1  = (const float*)d_in[3];
    const float* b1  = (const float*)d_in[4];
    const float* w2  = (const float*)d_in[5];
    const float* b2  = (const float*)d_in[6];
    const int* query1 = (const int*)d_in[7];
    const int* doc1   = (const int*)d_in[8];
    const int* query2 = (const int*)d_in[9];
    const int* doc2   = (const int*)d_in[10];
    float* out = (float*)d_out;

    // smem: tiles only (ssum/pfeat/xps overlay the dead tile regions)
    const int smem_bytes = (LD + LQ) * TSTR * 2 * 4;
    cudaFuncSetAttribute(knrm_main, cudaFuncAttributeMaxDynamicSharedMemorySize, smem_bytes);

    knrm_main<<<dim3(BATCH / 2, 2), 256, smem_bytes>>>(emb, query1, doc1, query2, doc2, 0);
    knrm_main<<<dim3(BATCH / 2, 2), 256, smem_bytes>>>(emb, query1, doc1, query2, doc2, BATCH / 2);
    knrm_mlp<<<16, 128>>>(w0, b0, w1, b1, w2, b2, out);
}

// round 15
// speedup vs baseline: 2.1457x; 1.1946x over previous
#include <cuda_runtime.h>
#include <cuda_bf16.h>
#include <math.h>

#define BATCH 2048
#define LQ 32
#define LD 256
#define EMBD 50
#define KN 21
#define L2E 1.4426950408889634f
#define TSTR 36        // u32 words per tile row (64 bf16 cols = 32 words + 4 pad)
#define XPS 17         // u64 stride per thread in xp overlay (conflict-free)

typedef unsigned long long u64;
typedef unsigned int u32;

__device__ float g_feat[2 * BATCH * KN];

__device__ __forceinline__ float ex2(float a) {
    float r; asm("ex2.approx.ftz.f32 %0, %1;" : "=f"(r) : "f"(a)); return r;
}
__device__ __forceinline__ float rsq(float a) {
    float r; asm("rsqrt.approx.f32 %0, %1;" : "=f"(r) : "f"(a)); return r;
}
__device__ __forceinline__ u64 fma2(u64 a, u64 b, u64 c) {
    u64 r; asm("fma.rn.f32x2 %0, %1, %2, %3;" : "=l"(r) : "l"(a), "l"(b), "l"(c)); return r;
}
__device__ __forceinline__ u64 mul2(u64 a, u64 b) {
    u64 r; asm("mul.rn.f32x2 %0, %1, %2;" : "=l"(r) : "l"(a), "l"(b)); return r;
}
__device__ __forceinline__ u64 pack2(float lo, float hi) {
    u64 r; asm("mov.b64 %0, {%1, %2};" : "=l"(r) : "f"(lo), "f"(hi)); return r;
}
__device__ __forceinline__ void unpack2(u64 v, float& lo, float& hi) {
    asm("mov.b64 {%0, %1}, %2;" : "=f"(lo), "=f"(hi) : "l"(v));
}
__device__ __forceinline__ u64 packu2(u32 lo, u32 hi) {
    u64 r; asm("mov.b64 %0, {%1, %2};" : "=l"(r) : "r"(lo), "r"(hi)); return r;
}
__device__ __forceinline__ u64 bcast2(float c) { return pack2(c, c); }
__device__ __forceinline__ u64 ex2p(u64 m) {
    float a, b; unpack2(m, a, b);
    return pack2(ex2(a), ex2(b));
}
// round+pack two f32 (in a u64) to bf16x2: result.lo16 = bf16(lo), .hi16 = bf16(hi)
__device__ __forceinline__ u32 cvt_bf2(u64 x2) {
    float lo, hi; unpack2(x2, lo, hi);
    u32 r; asm("cvt.rn.bf16x2.f32 %0, %1, %2;" : "=r"(r) : "f"(hi), "f"(lo));
    return r;
}

__device__ __forceinline__ float CKf(int k) {
    switch (k) {
        case 0: return 2.5261638e-20f;
        case 1: return 2.0469717e-16f;
        case 2: return 6.1019367e-13f;
        case 3: return 6.6915860e-10f;
        case 4: return 2.6995785e-07f;
        case 5: return 4.0065297e-05f;
        case 6: return 2.1874905e-03f;
        case 7: return 4.3936934e-02f;
        case 8: return 3.2465247e-01f;
        default: return 8.8249690e-01f;
    }
}

__device__ __forceinline__ void mma_bf16(float& c0, float& c1, float& c2, float& c3,
                                         u32 a0, u32 a1, u32 a2, u32 a3,
                                         u32 b0, u32 b1)
{
    asm("mma.sync.aligned.m16n8k16.row.col.f32.bf16.bf16.f32 "
        "{%0,%1,%2,%3},{%4,%5,%6,%7},{%8,%9},{%0,%1,%2,%3};"
        : "+f"(c0), "+f"(c1), "+f"(c2), "+f"(c3)
        : "r"(a0), "r"(a1), "r"(a2), "r"(a3), "r"(b0), "r"(b1));
}

__device__ __forceinline__ void ldsm4(u32& r0, u32& r1, u32& r2, u32& r3, u32 saddr)
{
    asm volatile("ldmatrix.sync.aligned.m8n8.x4.shared.b16 {%0,%1,%2,%3}, [%4];"
                 : "=r"(r0), "=r"(r1), "=r"(r2), "=r"(r3) : "r"(saddr));
}

extern "C" __global__ void __launch_bounds__(256, 2)
knrm_main(const float* __restrict__ emb,
          const int* __restrict__ query1, const int* __restrict__ doc1,
          const int* __restrict__ query2, const int* __restrict__ doc2,
          int boff)
{
    extern __shared__ u32 smw[];
    u32* dh = smw;                       // [256][36] bf16x2 hi  (xp overlay later)
    u32* dl = dh + LD * TSTR;            // [256][36] bf16x2 lo  (ssum/pfeat overlay later)
    u32* qh = dl + LD * TSTR;            // [32][36]
    u32* ql = qh + LQ * TSTR;            // [32][36]
    u64*  xps    = (u64*)smw;                  // overlay over dh after MMA
    float* ssum  = (float*)dl;                 // overlay over dl after MMA: [4][32][21]
    float* pfeat = ssum + 4 * LQ * KN;         // [672]

    const int b    = blockIdx.x + boff;
    const int pair = blockIdx.y;
    const int* qidx = pair ? query2 : query1;
    const int* didx = pair ? doc2   : doc1;
    const int tid  = threadIdx.x;
    const int w    = tid >> 5;
    const int lane = tid & 31;

    // ---- gather: warp w owns rows [36w, 36w+36); 8 lanes per row, 4 rows/group ----
    {
        int r0 = 36 * w + lane;
        int tok0 = (r0 < LD) ? didx[b * LD + r0] : qidx[b * LQ + (r0 - LD)];
        int tok1 = 0;
        if (lane < 4) {
            int r1 = 36 * w + 32 + lane;
            tok1 = (r1 < LD) ? didx[b * LD + r1] : qidx[b * LQ + (r1 - LD)];
        }

        const int rr  = lane >> 3;      // row within 4-row group (0..3)
        const int sub = lane & 7;       // float2 sub-index within row
        const u64 cM1 = bcast2(-1.0f);

        #pragma unroll
        for (int ch = 0; ch < 3; ch++) {          // 3 chunks x 3 groups (MLP=12)
            u64 e2[3][4];
            #pragma unroll
            for (int gg = 0; gg < 3; gg++) {
                const int g  = ch * 3 + gg;        // group 0..8
                const int rl = 4 * g + rr;         // local row 0..35
                int tk = (g < 8) ? __shfl_sync(0xffffffffu, tok0, rl)
                                 : __shfl_sync(0xffffffffu, tok1, rr);
                const u64* rp = (const u64*)(emb + (size_t)tk * EMBD);
                #pragma unroll
                for (int k = 0; k < 4; k++) {
                    int c2 = sub + 8 * k;          // float2 col 0..24 valid
                    e2[gg][k] = (c2 < 25) ? rp[c2] : 0ull;
                }
            }
            #pragma unroll
            for (int gg = 0; gg < 3; gg++) {
                const int g   = ch * 3 + gg;
                const int row = 36 * w + 4 * g + rr;
                u64 s2 = 0ull;
                #pragma unroll
                for (int k = 0; k < 4; k++)
                    s2 = fma2(e2[gg][k], e2[gg][k], s2);
                float sa, sb; unpack2(s2, sa, sb);
                float ss = sa + sb;
                ss += __shfl_xor_sync(0xffffffffu, ss, 1);
                ss += __shfl_xor_sync(0xffffffffu, ss, 2);
                ss += __shfl_xor_sync(0xffffffffu, ss, 4);
                u64 scale2 = bcast2(rsq(ss + 1e-26f));

                u32 *ht, *lt; int trow;
                if (row < LD) { ht = dh; lt = dl; trow = row; }
                else          { ht = qh; lt = ql; trow = row - LD; }
                u32* hrow = ht + trow * TSTR;
                u32* lrow = lt + trow * TSTR;

                #pragma unroll
                for (int k = 0; k < 4; k++) {
                    int c2 = sub + 8 * k;
                    if (c2 < 25) {
                        u64 x2 = mul2(e2[gg][k], scale2);
                        u32 hp = cvt_bf2(x2);
                        // reconstruct hi pair as f32 (bf16 -> f32 is <<16)
                        u64 hf2 = packu2(hp << 16, hp & 0xffff0000u);
                        u64 rr2 = fma2(hf2, cM1, x2);      // residual
                        u32 lp = cvt_bf2(rr2);
                        hrow[c2] = hp;
                        lrow[c2] = lp;
                    }
                }
                if (sub > 0) {   // zero K-pad words 25..31
                    hrow[24 + sub] = 0u;
                    lrow[24 + sub] = 0u;
                }
            }
        }
    }
    __syncthreads();

    // ==== tensor-core matmul: warp w -> q-tile m16 at qm, d-tile n64 at dt*64 ====
    const int qm = (w & 1) * 16;
    const int dt = w >> 1;                  // 0..3
    const int g  = lane >> 2;               // 0..7
    const int t  = lane & 3;                // 0..3

    float C[8][4];
    #pragma unroll
    for (int nt = 0; nt < 8; nt++)
        #pragma unroll
        for (int i = 0; i < 4; i++) C[nt][i] = 0.0f;

    const u32 qh_s = (u32)__cvta_generic_to_shared(qh);
    const u32 ql_s = (u32)__cvta_generic_to_shared(ql);
    const u32 dh_s = (u32)__cvta_generic_to_shared(dh);
    const u32 dl_s = (u32)__cvta_generic_to_shared(dl);

    const int arow  = qm + (lane & 15);
    const int acolw = (lane & 16) >> 2;                        // 0 or 4 words
    const u32 a_ofs = (u32)((arow * TSTR + acolw) * 4);

    const int brow  = dt * 64 + (lane & 7) + ((lane & 16) >> 1);  // +8 for lanes>=16
    const int bcolw = (lane & 8) >> 1;                            // 0 or 4 words
    const u32 b_ofs = (u32)((brow * TSTR + bcolw) * 4);

    #pragma unroll
    for (int ks = 0; ks < 4; ks++) {
        const u32 kb = (u32)(ks * 8 * 4);          // k16 step, bytes
        u32 ah0, ah1, ah2, ah3, al0, al1, al2, al3;
        ldsm4(ah0, ah1, ah2, ah3, qh_s + a_ofs + kb);
        ldsm4(al0, al1, al2, al3, ql_s + a_ofs + kb);
        #pragma unroll
        for (int np = 0; np < 4; np++) {           // 2 n8-tiles per ldmatrix.x4
            const u32 nb = b_ofs + kb + (u32)(np * 16 * TSTR * 4);
            u32 bh0, bh1, bh2, bh3, bl0, bl1, bl2, bl3;
            ldsm4(bh0, bh1, bh2, bh3, dh_s + nb);
            ldsm4(bl0, bl1, bl2, bl3, dl_s + nb);
            mma_bf16(C[2*np][0], C[2*np][1], C[2*np][2], C[2*np][3],
                     ah0, ah1, ah2, ah3, bh0, bh1);
            mma_bf16(C[2*np][0], C[2*np][1], C[2*np][2], C[2*np][3],
                     ah0, ah1, ah2, ah3, bl0, bl1);
            mma_bf16(C[2*np][0], C[2*np][1], C[2*np][2], C[2*np][3],
                     al0, al1, al2, al3, bh0, bh1);
            mma_bf16(C[2*np+1][0], C[2*np+1][1], C[2*np+1][2], C[2*np+1][3],
                     ah0, ah1, ah2, ah3, bh2, bh3);
            mma_bf16(C[2*np+1][0], C[2*np+1][1], C[2*np+1][2], C[2*np+1][3],
                     ah0, ah1, ah2, ah3, bl2, bl3);
            mma_bf16(C[2*np+1][0], C[2*np+1][1], C[2*np+1][2], C[2*np+1][3],
                     al0, al1, al2, al3, bh2, bh3);
        }
    }
    __syncthreads();   // all warps done reading dh/dl -> overlays safe

    // ---- park x pairs in smem (frees regs for eval constants) ----
    {
        u64* xbase = xps + tid * XPS;
        #pragma unroll
        for (int nt = 0; nt < 8; nt++) {
            xbase[2 * nt]     = pack2(C[nt][0], C[nt][2]);
            xbase[2 * nt + 1] = pack2(C[nt][1], C[nt][3]);
        }
    }

    // ---- eval: 20 Gaussian kernels via 2 packed chains + exact-match count ----
    const u64 cZ  = bcast2(-50.0f * L2E);
    const u64 c10 = bcast2(10.0f * L2E);
    const u64 cA  = bcast2(-95.0f * L2E);   // chain A seed mu = -0.95
    const u64 cB  = bcast2(5.0f * L2E);     // chain B seed mu =  0.05
    const int IB09 = 0x3F666666;            // __float_as_int(0.9f)

    u64 Kc[10];
    #pragma unroll
    for (int j = 0; j < 10; j++) Kc[j] = bcast2(CKf(j));

    u64 ks2[20];
    #pragma unroll
    for (int k = 0; k < 20; k++) ks2[k] = 0ull;
    int icl = 0, ich = 0;

    const u64* xbase = xps + tid * XPS;
    #pragma unroll
    for (int m = 0; m < 16; m++) {
        u64 x2 = xbase[m];
        {
            int ilo = (int)(unsigned)(x2 & 0xffffffffu);
            int ihi = (int)(unsigned)(x2 >> 32);
            icl += (ilo > IB09);
            ich += (ihi > IB09);
        }
        u64 y2 = mul2(x2, x2);
        u64 z2 = mul2(y2, cZ);
        u64 r2 = ex2p(mul2(x2, c10));
        u64 tA = ex2p(fma2(x2, cA, z2));
        u64 tB = ex2p(fma2(x2, cB, z2));

        // chain A uses CK(j) = Kc[j]; chain B uses CK(10+j) = CK(9-j) = Kc[9-j]
        #pragma unroll
        for (int j = 0; j < 10; j++) {
            ks2[j]      = fma2(tA, Kc[j],     ks2[j]);
            ks2[10 + j] = fma2(tB, Kc[9 - j], ks2[10 + j]);
            if (j < 9) { tA = mul2(tA, r2); tB = mul2(tB, r2); }
        }
    }

    // ---- reduce over the 4 lanes (t = 0..3) sharing each g ----
    float sl[KN], sh[KN];
    #pragma unroll
    for (int k = 0; k < 20; k++) unpack2(ks2[k], sl[k], sh[k]);
    sl[20] = (float)icl; sh[20] = (float)ich;
    #pragma unroll
    for (int k = 0; k < KN; k++) {
        float a = sl[k], c = sh[k];
        a += __shfl_xor_sync(0xffffffffu, a, 1);
        a += __shfl_xor_sync(0xffffffffu, a, 2);
        c += __shfl_xor_sync(0xffffffffu, c, 1);
        c += __shfl_xor_sync(0xffffffffu, c, 2);
        sl[k] = a; sh[k] = c;
    }
    {
        float* d0 = ssum + (dt * LQ + qm + g) * KN;
        float* d1 = ssum + (dt * LQ + qm + g + 8) * KN;
        #pragma unroll
        for (int k = 0; k < KN; k++)
            if ((k & 3) == t) { d0[k] = sl[k]; d1[k] = sh[k]; }
    }
    __syncthreads();

    // ---- sum d-tiles, log1p per (q,k) ----
    for (int idx = tid; idx < LQ * KN; idx += 256) {
        float v = ssum[idx] + ssum[LQ * KN + idx]
                + ssum[2 * LQ * KN + idx] + ssum[3 * LQ * KN + idx];
        pfeat[idx] = log1pf(v);
    }
    __syncthreads();
    if (tid < KN) {
        float f = 0.0f;
        #pragma unroll
        for (int q = 0; q < LQ; q++)
            f += pfeat[q * KN + tid];
        g_feat[(pair * BATCH + b) * KN + tid] = f;
    }
}

extern "C" __global__ void knrm_mlp(const float* __restrict__ w0, const float* __restrict__ b0,
                                    const float* __restrict__ w1, const float* __restrict__ b1,
                                    const float* __restrict__ w2, const float* __restrict__ b2,
                                    float* __restrict__ out)
{
    int b = blockIdx.x * blockDim.x + threadIdx.x;
    if (b >= BATCH) return;

    float logit[2];
    #pragma unroll
    for (int p = 0; p < 2; p++) {
        const float* f = g_feat + (p * BATCH + b) * KN;
        float h0[10];
        #pragma unroll
        for (int j = 0; j < 10; j++) {
            float s = b0[j];
            #pragma unroll
            for (int k = 0; k < KN; k++) s = fmaf(w0[j * KN + k], f[k], s);
            h0[j] = fmaxf(s, 0.0f);
        }
        float h1[5];
        #pragma unroll
        for (int j = 0; j < 5; j++) {
            float s = b1[j];
            #pragma unroll
            for (int k = 0; k < 10; k++) s = fmaf(w1[j * 10 + k], h0[k], s);
            h1[j] = fmaxf(s, 0.0f);
        }
        float s = b2[0];
        #pragma unroll
        for (int k = 0; k < 5; k++) s = fmaf(w2[k], h1[k], s);
        logit[p] = s;
    }
    float z = logit[0] - logit[1];
    out[b] = 1.0f / (1.0f + expf(-z));
}

extern "C" void kernel_launch(void* const* d_in, const int* in_sizes, int n_in,
                              void* d_out, int out_size)
{
    const float* emb = (const float*)d_in[0];
    const float* w0  = (const float*)d_in[1];
    const float* b0  = (const float*)d_in[2];
    const float* w1  = (const float*)d_in[3];
    const float* b1  = (const float*)d_in[4];
    const float* w2  = (const float*)d_in[5];
    const float* b2  = (const float*)d_in[6];
    const int* query1 = (const int*)d_in[7];
    const int* doc1   = (const int*)d_in[8];
    const int* query2 = (const int*)d_in[9];
    const int* doc2   = (const int*)d_in[10];
    float* out = (float*)d_out;

    // smem: tiles only (ssum/pfeat/xps overlay the dead tile regions)
    const int smem_bytes = (LD + LQ) * TSTR * 2 * 4;
    cudaFuncSetAttribute(knrm_main, cudaFuncAttributeMaxDynamicSharedMemorySize, smem_bytes);

    knrm_main<<<dim3(BATCH / 2, 2), 256, smem_bytes>>>(emb, query1, doc1, query2, doc2, 0);
    knrm_main<<<dim3(BATCH / 2, 2), 256, smem_bytes>>>(emb, query1, doc1, query2, doc2, BATCH / 2);
    knrm_mlp<<<16, 128>>>(w0, b0, w1, b1, w2, b2, out);
}

// round 16
// speedup vs baseline: 2.1550x; 1.0043x over previous
#include <cuda_runtime.h>
#include <cuda_bf16.h>
#include <math.h>

#define BATCH 2048
#define LQ 32
#define LD 256
#define EMBD 50
#define KN 21
#define L2E 1.4426950408889634f
#define TSTR 36        // u32 words per tile row (64 bf16 cols = 32 words + 4 pad)
#define XPS 18         // u64 stride per thread in xp overlay (16B-aligned, conflict-free)

typedef unsigned long long u64;
typedef unsigned int u32;

__device__ float g_feat[2 * BATCH * KN];

__device__ __forceinline__ float ex2(float a) {
    float r; asm("ex2.approx.ftz.f32 %0, %1;" : "=f"(r) : "f"(a)); return r;
}
__device__ __forceinline__ float rsq(float a) {
    float r; asm("rsqrt.approx.f32 %0, %1;" : "=f"(r) : "f"(a)); return r;
}
__device__ __forceinline__ u64 fma2(u64 a, u64 b, u64 c) {
    u64 r; asm("fma.rn.f32x2 %0, %1, %2, %3;" : "=l"(r) : "l"(a), "l"(b), "l"(c)); return r;
}
__device__ __forceinline__ u64 mul2(u64 a, u64 b) {
    u64 r; asm("mul.rn.f32x2 %0, %1, %2;" : "=l"(r) : "l"(a), "l"(b)); return r;
}
__device__ __forceinline__ u64 pack2(float lo, float hi) {
    u64 r; asm("mov.b64 %0, {%1, %2};" : "=l"(r) : "f"(lo), "f"(hi)); return r;
}
__device__ __forceinline__ void unpack2(u64 v, float& lo, float& hi) {
    asm("mov.b64 {%0, %1}, %2;" : "=f"(lo), "=f"(hi) : "l"(v));
}
__device__ __forceinline__ u64 packu2(u32 lo, u32 hi) {
    u64 r; asm("mov.b64 %0, {%1, %2};" : "=l"(r) : "r"(lo), "r"(hi)); return r;
}
__device__ __forceinline__ u64 bcast2(float c) { return pack2(c, c); }
__device__ __forceinline__ u64 ex2p(u64 m) {
    float a, b; unpack2(m, a, b);
    return pack2(ex2(a), ex2(b));
}
// round+pack two f32 (in a u64) to bf16x2: result.lo16 = bf16(lo), .hi16 = bf16(hi)
__device__ __forceinline__ u32 cvt_bf2(u64 x2) {
    float lo, hi; unpack2(x2, lo, hi);
    u32 r; asm("cvt.rn.bf16x2.f32 %0, %1, %2;" : "=r"(r) : "f"(hi), "f"(lo));
    return r;
}

__device__ __forceinline__ float CKf(int k) {
    switch (k) {
        case 0: return 2.5261638e-20f;
        case 1: return 2.0469717e-16f;
        case 2: return 6.1019367e-13f;
        case 3: return 6.6915860e-10f;
        case 4: return 2.6995785e-07f;
        case 5: return 4.0065297e-05f;
        case 6: return 2.1874905e-03f;
        case 7: return 4.3936934e-02f;
        case 8: return 3.2465247e-01f;
        default: return 8.8249690e-01f;
    }
}

__device__ __forceinline__ void mma_bf16(float& c0, float& c1, float& c2, float& c3,
                                         u32 a0, u32 a1, u32 a2, u32 a3,
                                         u32 b0, u32 b1)
{
    asm("mma.sync.aligned.m16n8k16.row.col.f32.bf16.bf16.f32 "
        "{%0,%1,%2,%3},{%4,%5,%6,%7},{%8,%9},{%0,%1,%2,%3};"
        : "+f"(c0), "+f"(c1), "+f"(c2), "+f"(c3)
        : "r"(a0), "r"(a1), "r"(a2), "r"(a3), "r"(b0), "r"(b1));
}

__device__ __forceinline__ void ldsm4(u32& r0, u32& r1, u32& r2, u32& r3, u32 saddr)
{
    asm volatile("ldmatrix.sync.aligned.m8n8.x4.shared.b16 {%0,%1,%2,%3}, [%4];"
                 : "=r"(r0), "=r"(r1), "=r"(r2), "=r"(r3) : "r"(saddr));
}

extern "C" __global__ void __launch_bounds__(256, 2)
knrm_main(const float* __restrict__ emb,
          const int* __restrict__ query1, const int* __restrict__ doc1,
          const int* __restrict__ query2, const int* __restrict__ doc2,
          int boff)
{
    extern __shared__ u32 smw[];
    u32* dh = smw;                       // [256][36] bf16x2 hi  (xp overlay later)
    u32* dl = dh + LD * TSTR;            // [256][36] bf16x2 lo  (ssum/pfeat overlay later)
    u32* qh = dl + LD * TSTR;            // [32][36]
    u32* ql = qh + LQ * TSTR;            // [32][36]
    u64*  xps    = (u64*)smw;                  // overlay over dh after MMA (256*18*8 = 36864 B)
    float* ssum  = (float*)dl;                 // overlay over dl after MMA: [4][32][21]
    float* pfeat = ssum + 4 * LQ * KN;         // [672]

    const int b    = blockIdx.x + boff;
    const int pair = blockIdx.y;
    const int* qidx = pair ? query2 : query1;
    const int* didx = pair ? doc2   : doc1;
    const int tid  = threadIdx.x;
    const int w    = tid >> 5;
    const int lane = tid & 31;

    // ---- gather: warp w owns rows [36w, 36w+36); 8 lanes per row, 4 rows/group ----
    {
        int r0 = 36 * w + lane;
        int tok0 = (r0 < LD) ? didx[b * LD + r0] : qidx[b * LQ + (r0 - LD)];
        int tok1 = 0;
        if (lane < 4) {
            int r1 = 36 * w + 32 + lane;
            tok1 = (r1 < LD) ? didx[b * LD + r1] : qidx[b * LQ + (r1 - LD)];
        }

        const int rr  = lane >> 3;      // row within 4-row group (0..3)
        const int sub = lane & 7;       // float2 sub-index within row
        const u64 cM1 = bcast2(-1.0f);

        #pragma unroll
        for (int ch = 0; ch < 3; ch++) {          // 3 chunks x 3 groups (MLP=12)
            u64 e2[3][4];
            #pragma unroll
            for (int gg = 0; gg < 3; gg++) {
                const int g  = ch * 3 + gg;        // group 0..8
                const int rl = 4 * g + rr;         // local row 0..35
                int tk = (g < 8) ? __shfl_sync(0xffffffffu, tok0, rl)
                                 : __shfl_sync(0xffffffffu, tok1, rr);
                const u64* rp = (const u64*)(emb + (size_t)tk * EMBD);
                #pragma unroll
                for (int k = 0; k < 4; k++) {
                    int c2 = sub + 8 * k;          // float2 col 0..24 valid
                    e2[gg][k] = (c2 < 25) ? rp[c2] : 0ull;
                }
            }
            #pragma unroll
            for (int gg = 0; gg < 3; gg++) {
                const int g   = ch * 3 + gg;
                const int row = 36 * w + 4 * g + rr;
                u64 s2 = 0ull;
                #pragma unroll
                for (int k = 0; k < 4; k++)
                    s2 = fma2(e2[gg][k], e2[gg][k], s2);
                float sa, sb; unpack2(s2, sa, sb);
                float ss = sa + sb;
                ss += __shfl_xor_sync(0xffffffffu, ss, 1);
                ss += __shfl_xor_sync(0xffffffffu, ss, 2);
                ss += __shfl_xor_sync(0xffffffffu, ss, 4);
                u64 scale2 = bcast2(rsq(ss + 1e-26f));

                u32 *ht, *lt; int trow;
                if (row < LD) { ht = dh; lt = dl; trow = row; }
                else          { ht = qh; lt = ql; trow = row - LD; }
                u32* hrow = ht + trow * TSTR;
                u32* lrow = lt + trow * TSTR;

                #pragma unroll
                for (int k = 0; k < 4; k++) {
                    int c2 = sub + 8 * k;
                    if (c2 < 25) {
                        u64 x2 = mul2(e2[gg][k], scale2);
                        u32 hp = cvt_bf2(x2);
                        // reconstruct hi pair as f32 (bf16 -> f32 is <<16)
                        u64 hf2 = packu2(hp << 16, hp & 0xffff0000u);
                        u64 rr2 = fma2(hf2, cM1, x2);      // residual
                        u32 lp = cvt_bf2(rr2);
                        hrow[c2] = hp;
                        lrow[c2] = lp;
                    }
                }
                if (sub > 0) {   // zero K-pad words 25..31
                    hrow[24 + sub] = 0u;
                    lrow[24 + sub] = 0u;
                }
            }
        }
    }
    __syncthreads();

    // ==== tensor-core matmul: warp w -> q-tile m16 at qm, d-tile n64 at dt*64 ====
    const int qm = (w & 1) * 16;
    const int dt = w >> 1;                  // 0..3
    const int g  = lane >> 2;               // 0..7
    const int t  = lane & 3;                // 0..3

    float C[8][4];
    #pragma unroll
    for (int nt = 0; nt < 8; nt++)
        #pragma unroll
        for (int i = 0; i < 4; i++) C[nt][i] = 0.0f;

    const u32 qh_s = (u32)__cvta_generic_to_shared(qh);
    const u32 ql_s = (u32)__cvta_generic_to_shared(ql);
    const u32 dh_s = (u32)__cvta_generic_to_shared(dh);
    const u32 dl_s = (u32)__cvta_generic_to_shared(dl);

    const int arow  = qm + (lane & 15);
    const int acolw = (lane & 16) >> 2;                        // 0 or 4 words
    const u32 a_ofs = (u32)((arow * TSTR + acolw) * 4);

    const int brow  = dt * 64 + (lane & 7) + ((lane & 16) >> 1);  // +8 for lanes>=16
    const int bcolw = (lane & 8) >> 1;                            // 0 or 4 words
    const u32 b_ofs = (u32)((brow * TSTR + bcolw) * 4);

    #pragma unroll
    for (int ks = 0; ks < 4; ks++) {
        const u32 kb = (u32)(ks * 8 * 4);          // k16 step, bytes
        u32 ah0, ah1, ah2, ah3, al0, al1, al2, al3;
        ldsm4(ah0, ah1, ah2, ah3, qh_s + a_ofs + kb);
        ldsm4(al0, al1, al2, al3, ql_s + a_ofs + kb);
        #pragma unroll
        for (int np = 0; np < 4; np++) {           // 2 n8-tiles per ldmatrix.x4
            const u32 nb = b_ofs + kb + (u32)(np * 16 * TSTR * 4);
            u32 bh0, bh1, bh2, bh3, bl0, bl1, bl2, bl3;
            ldsm4(bh0, bh1, bh2, bh3, dh_s + nb);
            ldsm4(bl0, bl1, bl2, bl3, dl_s + nb);
            mma_bf16(C[2*np][0], C[2*np][1], C[2*np][2], C[2*np][3],
                     ah0, ah1, ah2, ah3, bh0, bh1);
            mma_bf16(C[2*np][0], C[2*np][1], C[2*np][2], C[2*np][3],
                     ah0, ah1, ah2, ah3, bl0, bl1);
            mma_bf16(C[2*np][0], C[2*np][1], C[2*np][2], C[2*np][3],
                     al0, al1, al2, al3, bh0, bh1);
            mma_bf16(C[2*np+1][0], C[2*np+1][1], C[2*np+1][2], C[2*np+1][3],
                     ah0, ah1, ah2, ah3, bh2, bh3);
            mma_bf16(C[2*np+1][0], C[2*np+1][1], C[2*np+1][2], C[2*np+1][3],
                     ah0, ah1, ah2, ah3, bl2, bl3);
            mma_bf16(C[2*np+1][0], C[2*np+1][1], C[2*np+1][2], C[2*np+1][3],
                     al0, al1, al2, al3, bh2, bh3);
        }
    }
    __syncthreads();   // all warps done reading dh/dl -> overlays safe

    // ---- park x pairs in smem, vectorized (STS.128) ----
    {
        ulonglong2* xbase = (ulonglong2*)(xps + tid * XPS);
        #pragma unroll
        for (int nt = 0; nt < 8; nt++) {
            ulonglong2 v;
            v.x = pack2(C[nt][0], C[nt][2]);
            v.y = pack2(C[nt][1], C[nt][3]);
            xbase[nt] = v;
        }
    }

    // ---- eval: 20 Gaussian kernels via 2 packed chains + exact-match count ----
    const u64 cZ  = bcast2(-50.0f * L2E);
    const u64 c10 = bcast2(10.0f * L2E);
    const u64 cA  = bcast2(-95.0f * L2E);   // chain A seed mu = -0.95
    const u64 cB  = bcast2(5.0f * L2E);     // chain B seed mu =  0.05
    const int IB09 = 0x3F666666;            // __float_as_int(0.9f)

    u64 Kc[10];
    #pragma unroll
    for (int j = 0; j < 10; j++) Kc[j] = bcast2(CKf(j));

    u64 ks2[20];
    #pragma unroll
    for (int k = 0; k < 20; k++) ks2[k] = 0ull;
    int icl = 0, ich = 0;

    const ulonglong2* xbase = (const ulonglong2*)(xps + tid * XPS);
    #pragma unroll
    for (int mp = 0; mp < 8; mp++) {
        ulonglong2 xv = xbase[mp];        // LDS.128: two packed x-pairs
        #pragma unroll
        for (int h = 0; h < 2; h++) {
            u64 x2 = h ? xv.y : xv.x;
            {
                int ilo = (int)(unsigned)(x2 & 0xffffffffu);
                int ihi = (int)(unsigned)(x2 >> 32);
                icl += (ilo > IB09);
                ich += (ihi > IB09);
            }
            u64 y2 = mul2(x2, x2);
            u64 z2 = mul2(y2, cZ);
            u64 r2 = ex2p(mul2(x2, c10));
            u64 tA = ex2p(fma2(x2, cA, z2));
            u64 tB = ex2p(fma2(x2, cB, z2));

            // chain A uses CK(j) = Kc[j]; chain B uses CK(10+j) = CK(9-j) = Kc[9-j]
            #pragma unroll
            for (int j = 0; j < 10; j++) {
                ks2[j]      = fma2(tA, Kc[j],     ks2[j]);
                ks2[10 + j] = fma2(tB, Kc[9 - j], ks2[10 + j]);
                if (j < 9) { tA = mul2(tA, r2); tB = mul2(tB, r2); }
            }
        }
    }

    // ---- reduce over the 4 lanes (t = 0..3) sharing each g ----
    float sl[KN], sh[KN];
    #pragma unroll
    for (int k = 0; k < 20; k++) unpack2(ks2[k], sl[k], sh[k]);
    sl[20] = (float)icl; sh[20] = (float)ich;
    #pragma unroll
    for (int k = 0; k < KN; k++) {
        float a = sl[k], c = sh[k];
        a += __shfl_xor_sync(0xffffffffu, a, 1);
        a += __shfl_xor_sync(0xffffffffu, a, 2);
        c += __shfl_xor_sync(0xffffffffu, c, 1);
        c += __shfl_xor_sync(0xffffffffu, c, 2);
        sl[k] = a; sh[k] = c;
    }
    {
        float* d0 = ssum + (dt * LQ + qm + g) * KN;
        float* d1 = ssum + (dt * LQ + qm + g + 8) * KN;
        #pragma unroll
        for (int k = 0; k < KN; k++)
            if ((k & 3) == t) { d0[k] = sl[k]; d1[k] = sh[k]; }
    }
    __syncthreads();

    // ---- sum d-tiles, log1p per (q,k) ----
    for (int idx = tid; idx < LQ * KN; idx += 256) {
        float v = ssum[idx] + ssum[LQ * KN + idx]
                + ssum[2 * LQ * KN + idx] + ssum[3 * LQ * KN + idx];
        pfeat[idx] = log1pf(v);
    }
    __syncthreads();
    if (tid < KN) {
        float f = 0.0f;
        #pragma unroll
        for (int q = 0; q < LQ; q++)
            f += pfeat[q * KN + tid];
        g_feat[(pair * BATCH + b) * KN + tid] = f;
    }
}

extern "C" __global__ void knrm_mlp(const float* __restrict__ w0, const float* __restrict__ b0,
                                    const float* __restrict__ w1, const float* __restrict__ b1,
                                    const float* __restrict__ w2, const float* __restrict__ b2,
                                    float* __restrict__ out)
{
    int b = blockIdx.x * blockDim.x + threadIdx.x;
    if (b >= BATCH) return;

    float logit[2];
    #pragma unroll
    for (int p = 0; p < 2; p++) {
        const float* f = g_feat + (p * BATCH + b) * KN;
        float h0[10];
        #pragma unroll
        for (int j = 0; j < 10; j++) {
            float s = b0[j];
            #pragma unroll
            for (int k = 0; k < KN; k++) s = fmaf(w0[j * KN + k], f[k], s);
            h0[j] = fmaxf(s, 0.0f);
        }
        float h1[5];
        #pragma unroll
        for (int j = 0; j < 5; j++) {
            float s = b1[j];
            #pragma unroll
            for (int k = 0; k < 10; k++) s = fmaf(w1[j * 10 + k], h0[k], s);
            h1[j] = fmaxf(s, 0.0f);
        }
        float s = b2[0];
        #pragma unroll
        for (int k = 0; k < 5; k++) s = fmaf(w2[k], h1[k], s);
        logit[p] = s;
    }
    float z = logit[0] - logit[1];
    out[b] = 1.0f / (1.0f + expf(-z));
}

extern "C" void kernel_launch(void* const* d_in, const int* in_sizes, int n_in,
                              void* d_out, int out_size)
{
    const float* emb = (const float*)d_in[0];
    const float* w0  = (const float*)d_in[1];
    const float* b0  = (const float*)d_in[2];
    const float* w1  = (const float*)d_in[3];
    const float* b1  = (const float*)d_in[4];
    const float* w2  = (const float*)d_in[5];
    const float* b2  = (const float*)d_in[6];
    const int* query1 = (const int*)d_in[7];
    const int* doc1   = (const int*)d_in[8];
    const int* query2 = (const int*)d_in[9];
    const int* doc2   = (const int*)d_in[10];
    float* out = (float*)d_out;

    // smem: tiles only (ssum/pfeat/xps overlay the dead tile regions)
    const int smem_bytes = (LD + LQ) * TSTR * 2 * 4;
    cudaFuncSetAttribute(knrm_main, cudaFuncAttributeMaxDynamicSharedMemorySize, smem_bytes);

    knrm_main<<<dim3(BATCH / 2, 2), 256, smem_bytes>>>(emb, query1, doc1, query2, doc2, 0);
    knrm_main<<<dim3(BATCH / 2, 2), 256, smem_bytes>>>(emb, query1, doc1, query2, doc2, BATCH / 2);
    knrm_mlp<<<16, 128>>>(w0, b0, w1, b1, w2, b2, out);
}

// round 17
// speedup vs baseline: 2.2583x; 1.0479x over previous
#include <cuda_runtime.h>
#include <cuda_bf16.h>
#include <math.h>

#define BATCH 2048
#define LQ 32
#define LD 256
#define EMBD 50
#define KN 21
#define L2E 1.4426950408889634f
#define TSTR 36        // u32 words per tile row (64 bf16 cols = 32 words + 4 pad)
#define XPS 18         // u64 stride per thread in xp overlay (16B-aligned, conflict-free)

typedef unsigned long long u64;
typedef unsigned int u32;

__device__ float g_feat[2 * BATCH * KN];

__device__ __forceinline__ float ex2(float a) {
    float r; asm("ex2.approx.ftz.f32 %0, %1;" : "=f"(r) : "f"(a)); return r;
}
__device__ __forceinline__ float rsq(float a) {
    float r; asm("rsqrt.approx.f32 %0, %1;" : "=f"(r) : "f"(a)); return r;
}
__device__ __forceinline__ u64 fma2(u64 a, u64 b, u64 c) {
    u64 r; asm("fma.rn.f32x2 %0, %1, %2, %3;" : "=l"(r) : "l"(a), "l"(b), "l"(c)); return r;
}
__device__ __forceinline__ u64 mul2(u64 a, u64 b) {
    u64 r; asm("mul.rn.f32x2 %0, %1, %2;" : "=l"(r) : "l"(a), "l"(b)); return r;
}
__device__ __forceinline__ u64 pack2(float lo, float hi) {
    u64 r; asm("mov.b64 %0, {%1, %2};" : "=l"(r) : "f"(lo), "f"(hi)); return r;
}
__device__ __forceinline__ void unpack2(u64 v, float& lo, float& hi) {
    asm("mov.b64 {%0, %1}, %2;" : "=f"(lo), "=f"(hi) : "l"(v));
}
__device__ __forceinline__ u64 packu2(u32 lo, u32 hi) {
    u64 r; asm("mov.b64 %0, {%1, %2};" : "=l"(r) : "r"(lo), "r"(hi)); return r;
}
__device__ __forceinline__ u64 bcast2(float c) { return pack2(c, c); }
__device__ __forceinline__ u64 ex2p(u64 m) {
    float a, b; unpack2(m, a, b);
    return pack2(ex2(a), ex2(b));
}
// round+pack two f32 (in a u64) to bf16x2: result.lo16 = bf16(lo), .hi16 = bf16(hi)
__device__ __forceinline__ u32 cvt_bf2(u64 x2) {
    float lo, hi; unpack2(x2, lo, hi);
    u32 r; asm("cvt.rn.bf16x2.f32 %0, %1, %2;" : "=r"(r) : "f"(hi), "f"(lo));
    return r;
}

__device__ __forceinline__ float CKf(int k) {
    switch (k) {
        case 0: return 2.5261638e-20f;
        case 1: return 2.0469717e-16f;
        case 2: return 6.1019367e-13f;
        case 3: return 6.6915860e-10f;
        case 4: return 2.6995785e-07f;
        case 5: return 4.0065297e-05f;
        case 6: return 2.1874905e-03f;
        case 7: return 4.3936934e-02f;
        case 8: return 3.2465247e-01f;
        default: return 8.8249690e-01f;
    }
}

__device__ __forceinline__ void mma_bf16(float& c0, float& c1, float& c2, float& c3,
                                         u32 a0, u32 a1, u32 a2, u32 a3,
                                         u32 b0, u32 b1)
{
    asm("mma.sync.aligned.m16n8k16.row.col.f32.bf16.bf16.f32 "
        "{%0,%1,%2,%3},{%4,%5,%6,%7},{%8,%9},{%0,%1,%2,%3};"
        : "+f"(c0), "+f"(c1), "+f"(c2), "+f"(c3)
        : "r"(a0), "r"(a1), "r"(a2), "r"(a3), "r"(b0), "r"(b1));
}

__device__ __forceinline__ void ldsm4(u32& r0, u32& r1, u32& r2, u32& r3, u32 saddr)
{
    asm volatile("ldmatrix.sync.aligned.m8n8.x4.shared.b16 {%0,%1,%2,%3}, [%4];"
                 : "=r"(r0), "=r"(r1), "=r"(r2), "=r"(r3) : "r"(saddr));
}

extern "C" __global__ void __launch_bounds__(256, 2)
knrm_main(const float* __restrict__ emb,
          const int* __restrict__ query1, const int* __restrict__ doc1,
          const int* __restrict__ query2, const int* __restrict__ doc2)
{
    extern __shared__ u32 smw[];
    u32* dh = smw;                       // [256][36] bf16x2 hi  (xp overlay later)
    u32* dl = dh + LD * TSTR;            // [256][36] bf16x2 lo  (ssum/pfeat overlay later)
    u32* qh = dl + LD * TSTR;            // [32][36]
    u32* ql = qh + LQ * TSTR;            // [32][36]
    u64*  xps    = (u64*)smw;                  // overlay over dh after MMA (256*18*8 = 36864 B)
    float* ssum  = (float*)dl;                 // overlay over dl after MMA: [4][32][21]
    float* pfeat = ssum + 4 * LQ * KN;         // [672]

    const int b    = blockIdx.x;
    const int pair = blockIdx.y;
    const int* qidx = pair ? query2 : query1;
    const int* didx = pair ? doc2   : doc1;
    const int tid  = threadIdx.x;
    const int w    = tid >> 5;
    const int lane = tid & 31;

    // ---- gather: warp w owns rows [36w, 36w+36); 8 lanes per row, 4 rows/group ----
    {
        int r0 = 36 * w + lane;
        int tok0 = (r0 < LD) ? didx[b * LD + r0] : qidx[b * LQ + (r0 - LD)];
        int tok1 = 0;
        if (lane < 4) {
            int r1 = 36 * w + 32 + lane;
            tok1 = (r1 < LD) ? didx[b * LD + r1] : qidx[b * LQ + (r1 - LD)];
        }

        const int rr  = lane >> 3;      // row within 4-row group (0..3)
        const int sub = lane & 7;       // float2 sub-index within row
        const u64 cM1 = bcast2(-1.0f);

        #pragma unroll
        for (int ch = 0; ch < 3; ch++) {          // 3 chunks x 3 groups (MLP=12)
            u64 e2[3][4];
            #pragma unroll
            for (int gg = 0; gg < 3; gg++) {
                const int g  = ch * 3 + gg;        // group 0..8
                const int rl = 4 * g + rr;         // local row 0..35
                int tk = (g < 8) ? __shfl_sync(0xffffffffu, tok0, rl)
                                 : __shfl_sync(0xffffffffu, tok1, rr);
                const u64* rp = (const u64*)(emb + (size_t)tk * EMBD);
                #pragma unroll
                for (int k = 0; k < 4; k++) {
                    int c2 = sub + 8 * k;          // float2 col 0..24 valid
                    e2[gg][k] = (c2 < 25) ? rp[c2] : 0ull;
                }
            }
            #pragma unroll
            for (int gg = 0; gg < 3; gg++) {
                const int g   = ch * 3 + gg;
                const int row = 36 * w + 4 * g + rr;
                u64 s2 = 0ull;
                #pragma unroll
                for (int k = 0; k < 4; k++)
                    s2 = fma2(e2[gg][k], e2[gg][k], s2);
                float sa, sb; unpack2(s2, sa, sb);
                float ss = sa + sb;
                ss += __shfl_xor_sync(0xffffffffu, ss, 1);
                ss += __shfl_xor_sync(0xffffffffu, ss, 2);
                ss += __shfl_xor_sync(0xffffffffu, ss, 4);
                u64 scale2 = bcast2(rsq(ss + 1e-26f));

                u32 *ht, *lt; int trow;
                if (row < LD) { ht = dh; lt = dl; trow = row; }
                else          { ht = qh; lt = ql; trow = row - LD; }
                u32* hrow = ht + trow * TSTR;
                u32* lrow = lt + trow * TSTR;

                #pragma unroll
                for (int k = 0; k < 4; k++) {
                    int c2 = sub + 8 * k;
                    if (c2 < 25) {
                        u64 x2 = mul2(e2[gg][k], scale2);
                        u32 hp = cvt_bf2(x2);
                        // reconstruct hi pair as f32 (bf16 -> f32 is <<16)
                        u64 hf2 = packu2(hp << 16, hp & 0xffff0000u);
                        u64 rr2 = fma2(hf2, cM1, x2);      // residual
                        u32 lp = cvt_bf2(rr2);
                        hrow[c2] = hp;
                        lrow[c2] = lp;
                    }
                }
                if (sub > 0) {   // zero K-pad words 25..31
                    hrow[24 + sub] = 0u;
                    lrow[24 + sub] = 0u;
                }
            }
        }
    }
    __syncthreads();

    // ==== tensor-core matmul: warp w -> q-tile m16 at qm, d-tile n64 at dt*64 ====
    const int qm = (w & 1) * 16;
    const int dt = w >> 1;                  // 0..3
    const int g  = lane >> 2;               // 0..7
    const int t  = lane & 3;                // 0..3

    float C[8][4];
    #pragma unroll
    for (int nt = 0; nt < 8; nt++)
        #pragma unroll
        for (int i = 0; i < 4; i++) C[nt][i] = 0.0f;

    const u32 qh_s = (u32)__cvta_generic_to_shared(qh);
    const u32 ql_s = (u32)__cvta_generic_to_shared(ql);
    const u32 dh_s = (u32)__cvta_generic_to_shared(dh);
    const u32 dl_s = (u32)__cvta_generic_to_shared(dl);

    const int arow  = qm + (lane & 15);
    const int acolw = (lane & 16) >> 2;                        // 0 or 4 words
    const u32 a_ofs = (u32)((arow * TSTR + acolw) * 4);

    const int brow  = dt * 64 + (lane & 7) + ((lane & 16) >> 1);  // +8 for lanes>=16
    const int bcolw = (lane & 8) >> 1;                            // 0 or 4 words
    const u32 b_ofs = (u32)((brow * TSTR + bcolw) * 4);

    #pragma unroll
    for (int ks = 0; ks < 4; ks++) {
        const u32 kb = (u32)(ks * 8 * 4);          // k16 step, bytes
        u32 ah0, ah1, ah2, ah3, al0, al1, al2, al3;
        ldsm4(ah0, ah1, ah2, ah3, qh_s + a_ofs + kb);
        ldsm4(al0, al1, al2, al3, ql_s + a_ofs + kb);
        #pragma unroll
        for (int np = 0; np < 4; np++) {           // 2 n8-tiles per ldmatrix.x4
            const u32 nb = b_ofs + kb + (u32)(np * 16 * TSTR * 4);
            u32 bh0, bh1, bh2, bh3, bl0, bl1, bl2, bl3;
            ldsm4(bh0, bh1, bh2, bh3, dh_s + nb);
            ldsm4(bl0, bl1, bl2, bl3, dl_s + nb);
            mma_bf16(C[2*np][0], C[2*np][1], C[2*np][2], C[2*np][3],
                     ah0, ah1, ah2, ah3, bh0, bh1);
            mma_bf16(C[2*np][0], C[2*np][1], C[2*np][2], C[2*np][3],
                     ah0, ah1, ah2, ah3, bl0, bl1);
            mma_bf16(C[2*np][0], C[2*np][1], C[2*np][2], C[2*np][3],
                     al0, al1, al2, al3, bh0, bh1);
            mma_bf16(C[2*np+1][0], C[2*np+1][1], C[2*np+1][2], C[2*np+1][3],
                     ah0, ah1, ah2, ah3, bh2, bh3);
            mma_bf16(C[2*np+1][0], C[2*np+1][1], C[2*np+1][2], C[2*np+1][3],
                     ah0, ah1, ah2, ah3, bl2, bl3);
            mma_bf16(C[2*np+1][0], C[2*np+1][1], C[2*np+1][2], C[2*np+1][3],
                     al0, al1, al2, al3, bh2, bh3);
        }
    }
    __syncthreads();   // all warps done reading dh/dl -> overlays safe

    // ---- park x pairs in smem, vectorized (STS.128) ----
    {
        ulonglong2* xbase = (ulonglong2*)(xps + tid * XPS);
        #pragma unroll
        for (int nt = 0; nt < 8; nt++) {
            ulonglong2 v;
            v.x = pack2(C[nt][0], C[nt][2]);
            v.y = pack2(C[nt][1], C[nt][3]);
            xbase[nt] = v;
        }
    }

    // ---- eval: 20 Gaussian kernels via 2x2 split recurrence chains ----
    const u64 cZ  = bcast2(-50.0f * L2E);
    const u64 c10 = bcast2(10.0f * L2E);
    const u64 cA  = bcast2(-95.0f * L2E);   // chain A seed mu = -0.95
    const u64 cB  = bcast2(5.0f * L2E);     // chain B seed mu =  0.05
    const int IB09 = 0x3F666666;            // __float_as_int(0.9f)

    u64 Kc[10];
    #pragma unroll
    for (int j = 0; j < 10; j++) Kc[j] = bcast2(CKf(j));

    u64 ks2[20];
    #pragma unroll
    for (int k = 0; k < 20; k++) ks2[k] = 0ull;
    int icl = 0, ich = 0;

    const ulonglong2* xbase = (const ulonglong2*)(xps + tid * XPS);
    #pragma unroll
    for (int mp = 0; mp < 8; mp++) {
        ulonglong2 xv = xbase[mp];        // LDS.128: two packed x-pairs
        #pragma unroll
        for (int h = 0; h < 2; h++) {
            u64 x2 = h ? xv.y : xv.x;
            {
                int ilo = (int)(unsigned)(x2 & 0xffffffffu);
                int ihi = (int)(unsigned)(x2 >> 32);
                icl += (ilo > IB09);
                ich += (ihi > IB09);
            }
            u64 y2 = mul2(x2, x2);
            u64 z2 = mul2(y2, cZ);
            u64 r2 = ex2p(mul2(x2, c10));      // exp(10x)
            u64 rs = mul2(r2, r2);             // exp(20x) — even/odd chain step
            u64 tA0 = ex2p(fma2(x2, cA, z2));  // chain A even seed
            u64 tB0 = ex2p(fma2(x2, cB, z2));  // chain B even seed
            u64 tA1 = mul2(tA0, r2);           // chain A odd seed
            u64 tB1 = mul2(tB0, r2);           // chain B odd seed

            // 4 independent sub-chains of depth 4 (was 2 chains of depth 9)
            #pragma unroll
            for (int j = 0; j < 5; j++) {
                ks2[2*j]          = fma2(tA0, Kc[2*j],         ks2[2*j]);
                ks2[2*j + 1]      = fma2(tA1, Kc[2*j + 1],     ks2[2*j + 1]);
                ks2[10 + 2*j]     = fma2(tB0, Kc[9 - 2*j],     ks2[10 + 2*j]);
                ks2[10 + 2*j + 1] = fma2(tB1, Kc[9 - 2*j - 1], ks2[10 + 2*j + 1]);
                if (j < 4) {
                    tA0 = mul2(tA0, rs);
                    tA1 = mul2(tA1, rs);
                    tB0 = mul2(tB0, rs);
                    tB1 = mul2(tB1, rs);
                }
            }
        }
    }

    // ---- reduce over the 4 lanes (t = 0..3) sharing each g ----
    float sl[KN], sh[KN];
    #pragma unroll
    for (int k = 0; k < 20; k++) unpack2(ks2[k], sl[k], sh[k]);
    sl[20] = (float)icl; sh[20] = (float)ich;
    #pragma unroll
    for (int k = 0; k < KN; k++) {
        float a = sl[k], c = sh[k];
        a += __shfl_xor_sync(0xffffffffu, a, 1);
        a += __shfl_xor_sync(0xffffffffu, a, 2);
        c += __shfl_xor_sync(0xffffffffu, c, 1);
        c += __shfl_xor_sync(0xffffffffu, c, 2);
        sl[k] = a; sh[k] = c;
    }
    {
        float* d0 = ssum + (dt * LQ + qm + g) * KN;
        float* d1 = ssum + (dt * LQ + qm + g + 8) * KN;
        #pragma unroll
        for (int k = 0; k < KN; k++)
            if ((k & 3) == t) { d0[k] = sl[k]; d1[k] = sh[k]; }
    }
    __syncthreads();

    // ---- sum d-tiles, log1p per (q,k) ----
    for (int idx = tid; idx < LQ * KN; idx += 256) {
        float v = ssum[idx] + ssum[LQ * KN + idx]
                + ssum[2 * LQ * KN + idx] + ssum[3 * LQ * KN + idx];
        pfeat[idx] = log1pf(v);
    }
    __syncthreads();
    if (tid < KN) {
        float f = 0.0f;
        #pragma unroll
        for (int q = 0; q < LQ; q++)
            f += pfeat[q * KN + tid];
        g_feat[(pair * BATCH + b) * KN + tid] = f;
    }
}

extern "C" __global__ void knrm_mlp(const float* __restrict__ w0, const float* __restrict__ b0,
                                    const float* __restrict__ w1, const float* __restrict__ b1,
                                    const float* __restrict__ w2, const float* __restrict__ b2,
                                    float* __restrict__ out)
{
    int b = blockIdx.x * blockDim.x + threadIdx.x;
    if (b >= BATCH) return;

    float logit[2];
    #pragma unroll
    for (int p = 0; p < 2; p++) {
        const float* f = g_feat + (p * BATCH + b) * KN;
        float h0[10];
        #pragma unroll
        for (int j = 0; j < 10; j++) {
            float s = b0[j];
            #pragma unroll
            for (int k = 0; k < KN; k++) s = fmaf(w0[j * KN + k], f[k], s);
            h0[j] = fmaxf(s, 0.0f);
        }
        float h1[5];
        #pragma unroll
        for (int j = 0; j < 5; j++) {
            float s = b1[j];
            #pragma unroll
            for (int k = 0; k < 10; k++) s = fmaf(w1[j * 10 + k], h0[k], s);
            h1[j] = fmaxf(s, 0.0f);
        }
        float s = b2[0];
        #pragma unroll
        for (int k = 0; k < 5; k++) s = fmaf(w2[k], h1[k], s);
        logit[p] = s;
    }
    float z = logit[0] - logit[1];
    out[b] = 1.0f / (1.0f + expf(-z));
}

extern "C" void kernel_launch(void* const* d_in, const int* in_sizes, int n_in,
                              void* d_out, int out_size)
{
    const float* emb = (const float*)d_in[0];
    const float* w0  = (const float*)d_in[1];
    const float* b0  = (const float*)d_in[2];
    const float* w1  = (const float*)d_in[3];
    const float* b1  = (const float*)d_in[4];
    const float* w2  = (const float*)d_in[5];
    const float* b2  = (const float*)d_in[6];
    const int* query1 = (const int*)d_in[7];
    const int* doc1   = (const int*)d_in[8];
    const int* query2 = (const int*)d_in[9];
    const int* doc2   = (const int*)d_in[10];
    float* out = (float*)d_out;

    // smem: tiles only (ssum/pfeat/xps overlay the dead tile regions)
    const int smem_bytes = (LD + LQ) * TSTR * 2 * 4;
    cudaFuncSetAttribute(knrm_main, cudaFuncAttributeMaxDynamicSharedMemorySize, smem_bytes);

    // single merged launch: removes one kernel-boundary wave tail
    knrm_main<<<dim3(BATCH, 2), 256, smem_bytes>>>(emb, query1, doc1, query2, doc2);
    knrm_mlp<<<16, 128>>>(w0, b0, w1, b1, w2, b2, out);
}